// round 16
// baseline (speedup 1.0000x reference)
#include <cuda_runtime.h>
#include <cuda_bf16.h>
#include <mma.h>
#include <math.h>
#include <cstdint>

using namespace nvcuda;
typedef __nv_bfloat16 bf16;

#define NB   128
#define TPB  512
#define Bsz  128
#define Tsz  512
#define ISZ  128
#define Hsz  1024
#define ACH  1048576          // floats per chain accumulator region
#define SMEM_BYTES 143360     // worst case NSHIFT7/KSH6: A 73728B + W 69632B

// ---- preconverted weight planes: [k][n] per phase, bf16 hi/lo ----------------
#define WTOT 19005440
__device__ bf16 g_wh[WTOT];
__device__ bf16 g_wl[WTOT];
#define OQ1(i) ((size_t)(i)*131072)
#define OR1(i) (393216 + (size_t)(i)*131072)
#define OL1    655360
#define OQ2(i) (5373952 + (size_t)(i)*1048576)
#define OR2(i) (8519680 + (size_t)(i)*1048576)
#define OL2    10616832

// ---------------- persistent state --------------------------------------------
__device__ float g_h1 [Bsz*Hsz];
__device__ float g_c1 [Bsz*Hsz];
__device__ float g_h2 [Bsz*Hsz];
__device__ float g_c2 [Bsz*Hsz];
__device__ float g_x  [Bsz*ISZ];
__device__ float g_x2 [Bsz*Hsz];
__device__ float g_hm1[Bsz*Hsz];
__device__ float g_hm2[Bsz*Hsz];
__device__ bf16  g_h1h[Bsz*Hsz], g_h1l[Bsz*Hsz];
__device__ bf16  g_h2h[Bsz*Hsz], g_h2l[Bsz*Hsz];
__device__ bf16  g_xh [Bsz*ISZ], g_xl [Bsz*ISZ];
__device__ bf16  g_x2h[Bsz*Hsz], g_x2l[Bsz*Hsz];
__device__ bf16  g_hm1h[Bsz*Hsz], g_hm1l[Bsz*Hsz];
__device__ bf16  g_hm2h[Bsz*Hsz], g_hm2l[Bsz*Hsz];
__device__ float g_acc[2*ACH];   // split-K partial slices (full overwrite, no atomics)
__device__ int   g_cnt[128];
__device__ unsigned g_barcnt;
__device__ volatile unsigned g_bargen;

__device__ __forceinline__ float sigm(float z)  { return 1.f / (1.f + __expf(-z)); }
__device__ __forceinline__ float tanhff(float z){ return 2.f / (1.f + __expf(-2.f*z)) - 1.f; }

__device__ __forceinline__ void cpa16(unsigned int dst, const void* src) {
    asm volatile("cp.async.cg.shared.global [%0], [%1], 16;\n" :: "r"(dst), "l"(src));
}
__device__ __forceinline__ void cpa_commit() { asm volatile("cp.async.commit_group;\n"); }
__device__ __forceinline__ void cpa_waitall() { asm volatile("cp.async.wait_all;\n"); }

// ---------------- grid barrier (hot spin) ---------------------------------------
__device__ __forceinline__ void gridbar() {
    __syncthreads();
    if (threadIdx.x == 0) {
        __threadfence();
        unsigned gen = g_bargen;
        if (atomicAdd(&g_barcnt, 1u) == (unsigned)(gridDim.x - 1)) {
            g_barcnt = 0;
            __threadfence();
            atomicExch((unsigned*)&g_bargen, gen + 1u);
        } else {
            while (g_bargen == gen) {}
        }
        __threadfence();
    }
    __syncthreads();
}

// ---------------- weight preconversion (once per launch) -----------------------
__global__ void preconv_kernel(
    const float* c1Q, const float* c1R, const float* c1Wih, const float* c1Whh,
    const float* c2Q, const float* c2R, const float* c2Wih, const float* c2Whh)
{
    int seg = blockIdx.y;
    const float *src = 0, *src2 = 0;
    int K = 0, N = 0, LD = 0, K1 = 0, lstm = 0;
    size_t dst = 0;
    switch (seg) {
        case 0: case 1: case 2:
            src = c1Q + (size_t)seg*131072; K = 1024; N = 128; LD = 1024; dst = OQ1(seg); break;
        case 3: case 4:
            src = c1R + (size_t)(seg-3)*131072; K = 128; N = 1024; LD = 128; dst = OR1(seg-3); break;
        case 5:
            src = c1Wih; src2 = c1Whh; K = 1152; N = 4096; K1 = 128; lstm = 1; dst = OL1; break;
        case 6: case 7: case 8:
            src = c2Q + (size_t)(seg-6)*1048576; K = 1024; N = 1024; LD = 1024; dst = OQ2(seg-6); break;
        case 9: case 10:
            src = c2R + (size_t)(seg-9)*1048576; K = 1024; N = 1024; LD = 1024; dst = OR2(seg-9); break;
        default:
            src = c2Wih; src2 = c2Whh; K = 2048; N = 4096; K1 = 1024; lstm = 1; dst = OL2; break;
    }
    size_t tot = (size_t)K * N;
    for (size_t i = (size_t)blockIdx.x*blockDim.x + threadIdx.x; i < tot;
         i += (size_t)gridDim.x*blockDim.x) {
        int k = (int)(i / N), n = (int)(i % N);
        float v;
        if (!lstm) {
            v = src[(size_t)n*LD + k];
        } else {
            int g = n & 3, u = n >> 2;
            int row = g*Hsz + u;
            v = (k < K1) ? src[(size_t)row*K1 + k] : src2[(size_t)row*Hsz + (k - K1)];
        }
        bf16 h = __float2bfloat16(v);
        g_wh[dst + i] = h;
        g_wl[dst + i] = __float2bfloat16(v - __bfloat162float(h));
    }
}

// ---------------- phase descriptor ---------------------------------------------
struct P {
    const bf16 *A1h, *A1l, *A2h, *A2l; int K1, Ktot;
    size_t woff;
    int N, kch, lstm;
    const float *b1, *b2;
    const float *mult; int mstride;
    float *out; bf16 *outh, *outl; int ostride;
    float *fc, *fh; bf16 *fhh, *fhl;
};

// one GEMM phase on a 64-CTA half-grid: 128 x NSTRIP tile, split-K into disjoint
// g_acc slices (no atomics), (1<<KSH)-k macro-tiles, cp.async bf16 hi/lo,
// 3-term bf16 wmma (hi*hi + hi*lo + lo*hi), fused epilogue on last CTA per tile.
template<int NSHIFT, int KSH>
__device__ __noinline__ void run_phase(const P p, int cta, float* accbase, int* cnt) {
    constexpr int NSTRIP = 1 << NSHIFT;
    constexpr int KW     = 1 << KSH;               // k per macro-tile (32 or 64)
    constexpr int WPITCH = NSTRIP + 8;
    constexpr int NW     = (NSHIFT >= 6) ? 4 : 2;
    constexpr int MW     = 16 / NW;
    constexpr int MFR    = 8 / MW;
    constexpr int NFR    = NSTRIP / (16 * NW);
    constexpr int AP     = KW + 8;                 // A pitch (bf16 elems)
    constexpr int ABUFE  = 2 * 128 * AP;           // hi+lo elems per A buffer
    constexpr int WBUFE  = 2 * KW * WPITCH;        // hi+lo elems per W buffer
    constexpr int TS     = 128 * NSTRIP;
    constexpr int ACH_CH = 128 * KW / 8;           // A 16B chunks per plane
    constexpr int WCH    = KW * (NSTRIP / 8);      // W 16B chunks per plane
    extern __shared__ float smf[];
    bf16* const sb = (bf16*)smf;
    bf16* const Wb = sb + 2 * ABUFE;
    __shared__ int s_last;

    const int ntiles = p.N >> NSHIFT;
    if (cta >= ntiles * p.kch) return;

    const int tid = threadIdx.x;
    const int wid = tid >> 5;
    const int tile = cta / p.kch, kc = cta - tile * p.kch;
    const int n0 = tile << NSHIFT;
    const int KL = p.Ktot / p.kch;
    const int k0 = kc * KL;
    const int niter = KL >> KSH;
    const int wm = wid % MW, wn = wid / MW;

    wmma::fragment<wmma::accumulator, 16, 16, 16, float> C[MFR * NFR];
    #pragma unroll
    for (int i = 0; i < MFR * NFR; i++) wmma::fill_fragment(C[i], 0.f);

    const bf16* WHg = g_wh + p.woff;
    const bf16* WLg = g_wl + p.woff;
    const unsigned int asmA = (unsigned int)__cvta_generic_to_shared(sb);
    const unsigned int asmW = (unsigned int)__cvta_generic_to_shared(Wb);

    auto issueA = [&](int buf, int kg) {
        constexpr int TOT = 2 * ACH_CH;
        #pragma unroll
        for (int i = 0; i < (TOT + TPB - 1) / TPB; i++) {
            int o = tid + i * TPB;
            if ((TOT % TPB) == 0 || o < TOT) {
                int pl = o / ACH_CH;
                int rem = o - pl * ACH_CH;
                int r = rem / (KW / 8), c = rem - r * (KW / 8);
                int k = kg + (c << 3);
                const bf16* src;
                if (k < p.K1) src = (pl ? p.A1l : p.A1h) + (size_t)r * p.K1 + k;
                else          src = (pl ? p.A2l : p.A2h) + (size_t)r * Hsz + (k - p.K1);
                unsigned int d = asmA +
                    (unsigned int)(buf * ABUFE + pl * 128 * AP + r * AP + (c << 3)) * 2u;
                cpa16(d, src);
            }
        }
    };
    auto issueW = [&](int buf, int kg) {
        constexpr int TOT = 2 * WCH;
        #pragma unroll
        for (int i = 0; i < (TOT + TPB - 1) / TPB; i++) {
            int o = tid + i * TPB;
            if ((TOT % TPB) == 0 || o < TOT) {
                int pl = o / WCH;
                int rem = o - pl * WCH;
                int kk = rem / (NSTRIP / 8), c = rem - kk * (NSTRIP / 8);
                size_t s = (size_t)(kg + kk) * p.N + n0 + (c << 3);
                unsigned int d = asmW +
                    (unsigned int)(buf * WBUFE + pl * KW * WPITCH + kk * WPITCH + (c << 3)) * 2u;
                cpa16(d, (pl ? WLg : WHg) + s);
            }
        }
    };
    auto compute = [&](int buf) {
        const bf16* AH = sb + buf * ABUFE;
        const bf16* AL = AH + 128 * AP;
        const bf16* WH = Wb + buf * WBUFE;
        const bf16* WL = WH + KW * WPITCH;
        #pragma unroll
        for (int ks = 0; ks < KW / 16; ++ks) {
            wmma::fragment<wmma::matrix_b, 16,16,16, bf16, wmma::row_major> bH[NFR], bL[NFR];
            #pragma unroll
            for (int nf = 0; nf < NFR; ++nf) {
                int ncol = (wn * NFR + nf) * 16;
                wmma::load_matrix_sync(bH[nf], WH + ks * 16 * WPITCH + ncol, WPITCH);
                wmma::load_matrix_sync(bL[nf], WL + ks * 16 * WPITCH + ncol, WPITCH);
            }
            #pragma unroll
            for (int mf = 0; mf < MFR; ++mf) {
                int mrow = (wm * MFR + mf) * 16;
                wmma::fragment<wmma::matrix_a, 16,16,16, bf16, wmma::row_major> aH, aL;
                wmma::load_matrix_sync(aH, AH + mrow * AP + ks * 16, AP);
                wmma::load_matrix_sync(aL, AL + mrow * AP + ks * 16, AP);
                #pragma unroll
                for (int nf = 0; nf < NFR; ++nf) {
                    // 3-term: hi*hi + hi*lo + lo*hi (lo*lo ~2^-18, negligible)
                    wmma::mma_sync(C[mf*NFR+nf], aH, bH[nf], C[mf*NFR+nf]);
                    wmma::mma_sync(C[mf*NFR+nf], aH, bL[nf], C[mf*NFR+nf]);
                    wmma::mma_sync(C[mf*NFR+nf], aL, bH[nf], C[mf*NFR+nf]);
                }
            }
        }
    };

    // ---- pipelined K loop ----
    issueA(0, k0); issueW(0, k0); cpa_commit();
    cpa_waitall();
    __syncthreads();
    for (int it = 0; it < niter; ++it) {
        const int cur = it & 1;
        const bool more = (it + 1 < niter);
        if (more) {
            issueA(cur ^ 1, k0 + ((it + 1) << KSH));
            issueW(cur ^ 1, k0 + ((it + 1) << KSH));
            cpa_commit();
        }
        compute(cur);
        cpa_waitall();
        __syncthreads();
    }

    // ---- dump C to smem out tile (128 x NSTRIP floats) ----
    #pragma unroll
    for (int mf = 0; mf < MFR; ++mf)
        #pragma unroll
        for (int nf = 0; nf < NFR; ++nf)
            wmma::store_matrix_sync(smf + ((wm * MFR + mf) * 16) * NSTRIP + (wn * NFR + nf) * 16,
                                    C[mf*NFR+nf], NSTRIP, wmma::mem_row_major);
    __syncthreads();

    // ---- write partial slice (disjoint per CTA, plain stores) ----
    float* slice = accbase + (size_t)(tile * p.kch + kc) * TS;
    for (int e = tid * 4; e < TS; e += TPB * 4)
        __stcg((float4*)(slice + e), *(const float4*)(smf + e));
    __threadfence();
    __syncthreads();
    if (tid == 0) s_last = (atomicAdd(&cnt[tile], 1) == p.kch - 1) ? 1 : 0;
    __syncthreads();

    if (s_last) {
        if (tid == 0) cnt[tile] = 0;
        __threadfence();
        float* base0 = accbase + (size_t)(tile * p.kch) * TS;
        for (int e = tid * 4; e < TS; e += TPB * 4) {
            float4 s4 = __ldcg((const float4*)(base0 + e));
            for (int k2 = 1; k2 < p.kch; ++k2) {
                float4 t4 = __ldcg((const float4*)(base0 + (size_t)k2 * TS + e));
                s4.x += t4.x; s4.y += t4.y; s4.z += t4.z; s4.w += t4.w;
            }
            int m = e >> NSHIFT, ln = e & (NSTRIP - 1);
            if (!p.lstm) {
                int n = n0 + ln;
                float4 mu = __ldcg((const float4*)(p.mult + (size_t)m * p.mstride + n));
                float v0 = 2.f * sigm(s4.x + p.b1[n+0]) * mu.x;
                float v1 = 2.f * sigm(s4.y + p.b1[n+1]) * mu.y;
                float v2 = 2.f * sigm(s4.z + p.b1[n+2]) * mu.z;
                float v3 = 2.f * sigm(s4.w + p.b1[n+3]) * mu.w;
                size_t o = (size_t)m * p.ostride + n;
                __stcg((float4*)(p.out + o), make_float4(v0, v1, v2, v3));
                bf16 a0 = __float2bfloat16(v0), a1 = __float2bfloat16(v1);
                bf16 a2 = __float2bfloat16(v2), a3 = __float2bfloat16(v3);
                unsigned hp0 = (unsigned)__bfloat16_as_ushort(a0) |
                               ((unsigned)__bfloat16_as_ushort(a1) << 16);
                unsigned hp1 = (unsigned)__bfloat16_as_ushort(a2) |
                               ((unsigned)__bfloat16_as_ushort(a3) << 16);
                __stcg((uint2*)((unsigned short*)p.outh + o), make_uint2(hp0, hp1));
                bf16 l0 = __float2bfloat16(v0 - __bfloat162float(a0));
                bf16 l1 = __float2bfloat16(v1 - __bfloat162float(a1));
                bf16 l2 = __float2bfloat16(v2 - __bfloat162float(a2));
                bf16 l3 = __float2bfloat16(v3 - __bfloat162float(a3));
                unsigned lp0 = (unsigned)__bfloat16_as_ushort(l0) |
                               ((unsigned)__bfloat16_as_ushort(l1) << 16);
                unsigned lp1 = (unsigned)__bfloat16_as_ushort(l2) |
                               ((unsigned)__bfloat16_as_ushort(l3) << 16);
                __stcg((uint2*)((unsigned short*)p.outl + o), make_uint2(lp0, lp1));
            } else {
                int u = (n0 + ln) >> 2;
                float zi = s4.x + p.b1[u]         + p.b2[u];
                float zf = s4.y + p.b1[Hsz+u]     + p.b2[Hsz+u];
                float zg = s4.z + p.b1[2*Hsz+u]   + p.b2[2*Hsz+u];
                float zo = s4.w + p.b1[3*Hsz+u]   + p.b2[3*Hsz+u];
                float cn = sigm(zf) * __ldcg(p.fc + (size_t)m*Hsz + u) + sigm(zi) * tanhff(zg);
                float hn = sigm(zo) * tanhff(cn);
                __stcg(p.fc + (size_t)m*Hsz + u, cn);
                __stcg(p.fh + (size_t)m*Hsz + u, hn);
                bf16 bh = __float2bfloat16(hn);
                __stcg((unsigned short*)p.fhh + (size_t)m*Hsz + u, __bfloat16_as_ushort(bh));
                __stcg((unsigned short*)p.fhl + (size_t)m*Hsz + u,
                       __bfloat16_as_ushort(__float2bfloat16(hn - __bfloat162float(bh))));
            }
        }
    }
}

__device__ __forceinline__ P mogP(const bf16* Ah, const bf16* Al, int K, size_t woff,
                                  int N, int kch, const float* bias,
                                  const float* mult, int mstride,
                                  float* out, bf16* outh, bf16* outl, int ostride) {
    P p;
    p.A1h = Ah; p.A1l = Al; p.A2h = Ah; p.A2l = Al; p.K1 = K; p.Ktot = K;
    p.woff = woff; p.N = N; p.kch = kch; p.lstm = 0;
    p.b1 = bias; p.b2 = bias;
    p.mult = mult; p.mstride = mstride;
    p.out = out; p.outh = outh; p.outl = outl; p.ostride = ostride;
    p.fc = 0; p.fh = 0; p.fhh = 0; p.fhl = 0;
    return p;
}

__device__ __forceinline__ P lstmP(const bf16* A1h, const bf16* A1l, int K1,
                                   const bf16* A2h, const bf16* A2l, int Ktot,
                                   size_t woff, const float* bih, const float* bhh,
                                   float* fc, float* fh, bf16* fhh, bf16* fhl, int kch) {
    P p;
    p.A1h = A1h; p.A1l = A1l; p.A2h = A2h; p.A2l = A2l; p.K1 = K1; p.Ktot = Ktot;
    p.woff = woff; p.N = 4096; p.kch = kch; p.lstm = 1;
    p.b1 = bih; p.b2 = bhh;
    p.mult = 0; p.mstride = 0; p.out = 0; p.outh = 0; p.outl = 0; p.ostride = 0;
    p.fc = fc; p.fh = fh; p.fhh = fhh; p.fhl = fhl;
    return p;
}

__global__ void __launch_bounds__(TPB, 1) mog_kernel(
    const float* in_seq,
    const float* c1Qb, const float* c1Rb, const float* c1bih, const float* c1bhh,
    const float* c2Qb, const float* c2Rb, const float* c2bih, const float* c2bhh,
    const float* linW, const float* linb, float* out)
{
    for (int i = blockIdx.x*TPB + threadIdx.x; i < Bsz*Hsz; i += NB*TPB) {
        g_h1[i] = 0.f; g_c1[i] = 0.f; g_h2[i] = 0.f; g_c2[i] = 0.f;
        unsigned short z = 0;
        ((unsigned short*)g_h1h)[i] = z; ((unsigned short*)g_h1l)[i] = z;
        ((unsigned short*)g_h2h)[i] = z; ((unsigned short*)g_h2l)[i] = z;
    }
    gridbar();

    const int ca = (blockIdx.x < 64);          // chain A = layer1(step s); B = layer2(step s-1)
    const int rc = ca ? blockIdx.x : blockIdx.x - 64;
    float* accA = g_acc;        float* accB = g_acc + ACH;
    int*   cntA = g_cnt;        int*   cntB = g_cnt + 64;

    for (int s = 0; s <= Tsz; ++s) {
        const int dA = (s < Tsz), dB = (s > 0);
        // slot 1: aQ0(s) || bQ0(s-1)
        if (ca) { if (dA) run_phase<5,5>(mogP(g_h1h, g_h1l, Hsz, OQ1(0), ISZ, 16, c1Qb,
                                              in_seq + (size_t)s*ISZ, Tsz*ISZ,
                                              g_x, g_xh, g_xl, ISZ), rc, accA, cntA); }
        else    { if (dB) run_phase<7,6>(mogP(g_h2h, g_h2l, Hsz, OQ2(0), Hsz, 8, c2Qb,
                                              g_h1, Hsz, g_x2, g_x2h, g_x2l, Hsz), rc, accB, cntB); }
        gridbar();
        // slot 2: aR0(s) || bR0(s-1)
        if (ca) { if (dA) run_phase<5,5>(mogP(g_xh, g_xl, ISZ, OR1(0), Hsz, 2, c1Rb,
                                              g_h1, Hsz, g_hm1, g_hm1h, g_hm1l, Hsz), rc, accA, cntA); }
        else    { if (dB) run_phase<7,6>(mogP(g_x2h, g_x2l, Hsz, OR2(0), Hsz, 8, c2Rb,
                                              g_h2, Hsz, g_hm2, g_hm2h, g_hm2l, Hsz), rc, accB, cntB); }
        gridbar();
        // slot 3: aQ1(s) || bQ1(s-1)
        if (ca) { if (dA) run_phase<5,5>(mogP(g_hm1h, g_hm1l, Hsz, OQ1(1), ISZ, 16, c1Qb + ISZ,
                                              g_x, ISZ, g_x, g_xh, g_xl, ISZ), rc, accA, cntA); }
        else    { if (dB) run_phase<7,6>(mogP(g_hm2h, g_hm2l, Hsz, OQ2(1), Hsz, 8, c2Qb + Hsz,
                                              g_x2, Hsz, g_x2, g_x2h, g_x2l, Hsz), rc, accB, cntB); }
        gridbar();
        // slot 4: aR1(s) || bR1(s-1)
        if (ca) { if (dA) run_phase<5,5>(mogP(g_xh, g_xl, ISZ, OR1(1), Hsz, 2, c1Rb + Hsz,
                                              g_hm1, Hsz, g_hm1, g_hm1h, g_hm1l, Hsz), rc, accA, cntA); }
        else    { if (dB) run_phase<7,6>(mogP(g_x2h, g_x2l, Hsz, OR2(1), Hsz, 8, c2Rb + Hsz,
                                              g_hm2, Hsz, g_hm2, g_hm2h, g_hm2l, Hsz), rc, accB, cntB); }
        gridbar();
        // slot 5: aQ2(s) || bQ2(s-1)
        if (ca) { if (dA) run_phase<5,5>(mogP(g_hm1h, g_hm1l, Hsz, OQ1(2), ISZ, 16, c1Qb + 2*ISZ,
                                              g_x, ISZ, g_x, g_xh, g_xl, ISZ), rc, accA, cntA); }
        else    { if (dB) run_phase<7,6>(mogP(g_hm2h, g_hm2l, Hsz, OQ2(2), Hsz, 8, c2Qb + 2*Hsz,
                                              g_x2, Hsz, g_x2, g_x2h, g_x2l, Hsz), rc, accB, cntB); }
        gridbar();
        // slot 6: aLSTM1(s) || bLSTM2(s-1)   (k64 macro-tiles: niter 9 / 16)
        if (ca) { if (dA) run_phase<7,6>(lstmP(g_xh, g_xl, ISZ, g_hm1h, g_hm1l, ISZ + Hsz, OL1,
                                               c1bih, c1bhh, g_c1, g_h1, g_h1h, g_h1l, 2),
                                         rc, accA, cntA); }
        else    { if (dB) run_phase<7,6>(lstmP(g_x2h, g_x2l, Hsz, g_hm2h, g_hm2l, 2*Hsz, OL2,
                                               c2bih, c2bhh, g_c2, g_h2, g_h2h, g_h2l, 2),
                                         rc, accB, cntB); }
        gridbar();
    }

    // final linear: out[b] = h2[b,:] . linW + linb
    if (blockIdx.x == 0 && threadIdx.x < 256) {
        int tid = threadIdx.x;
        int b = tid >> 1, half = tid & 1;
        const float* hrow = g_h2 + b*Hsz + half*512;
        const float* w    = linW + half*512;
        float s = 0.f;
        for (int j = 0; j < 512; ++j) s += __ldcg(hrow + j) * w[j];
        s += __shfl_xor_sync(0xffffffffu, s, 1);
        if (half == 0) out[b] = s + linb[0];
    }
}

extern "C" void kernel_launch(void* const* d_in, const int* in_sizes, int n_in,
                              void* d_out, int out_size) {
    (void)in_sizes; (void)n_in; (void)out_size;
    cudaFuncSetAttribute(mog_kernel, cudaFuncAttributeMaxDynamicSharedMemorySize,
                         SMEM_BYTES);
    const float* in_seq = (const float*)d_in[0];
    const float* c1Q    = (const float*)d_in[1];
    const float* c1Qb   = (const float*)d_in[2];
    const float* c1R    = (const float*)d_in[3];
    const float* c1Rb   = (const float*)d_in[4];
    const float* c1Wih  = (const float*)d_in[5];
    const float* c1Whh  = (const float*)d_in[6];
    const float* c1bih  = (const float*)d_in[7];
    const float* c1bhh  = (const float*)d_in[8];
    const float* c2Q    = (const float*)d_in[9];
    const float* c2Qb   = (const float*)d_in[10];
    const float* c2R    = (const float*)d_in[11];
    const float* c2Rb   = (const float*)d_in[12];
    const float* c2Wih  = (const float*)d_in[13];
    const float* c2Whh  = (const float*)d_in[14];
    const float* c2bih  = (const float*)d_in[15];
    const float* c2bhh  = (const float*)d_in[16];
    const float* linW   = (const float*)d_in[17];
    const float* linb   = (const float*)d_in[18];

    preconv_kernel<<<dim3(256, 12), 256>>>(c1Q, c1R, c1Wih, c1Whh,
                                           c2Q, c2R, c2Wih, c2Whh);
    mog_kernel<<<NB, TPB, SMEM_BYTES>>>(in_seq,
                                        c1Qb, c1Rb, c1bih, c1bhh,
                                        c2Qb, c2Rb, c2bih, c2bhh,
                                        linW, linb, (float*)d_out);
}

// round 17
// speedup vs baseline: 1.1736x; 1.1736x over previous
#include <cuda_runtime.h>
#include <cuda_bf16.h>
#include <mma.h>
#include <math.h>
#include <cstdint>

using namespace nvcuda;
typedef __nv_bfloat16 bf16;

#define NB   128
#define TPB  512
#define Bsz  128
#define Tsz  512
#define ISZ  128
#define Hsz  1024
#define ACH  1048576          // floats per chain accumulator region
#define SMEM_BYTES 143360     // worst case NSHIFT7/KSH6: A 73728B + W 69632B

// ---- preconverted weight planes: [k][n] per phase, bf16 hi/lo ----------------
#define WTOT 19005440
__device__ bf16 g_wh[WTOT];
__device__ bf16 g_wl[WTOT];
#define OQ1(i) ((size_t)(i)*131072)
#define OR1(i) (393216 + (size_t)(i)*131072)
#define OL1    655360
#define OQ2(i) (5373952 + (size_t)(i)*1048576)
#define OR2(i) (8519680 + (size_t)(i)*1048576)
#define OL2    10616832

// ---------------- persistent state --------------------------------------------
__device__ float g_h1 [Bsz*Hsz];
__device__ float g_c1 [Bsz*Hsz];
__device__ float g_h2 [Bsz*Hsz];
__device__ float g_c2 [Bsz*Hsz];
__device__ float g_x  [Bsz*ISZ];
__device__ float g_x2 [Bsz*Hsz];
__device__ float g_hm1[Bsz*Hsz];
__device__ float g_hm2[Bsz*Hsz];
__device__ bf16  g_h1h[Bsz*Hsz], g_h1l[Bsz*Hsz];
__device__ bf16  g_h2h[Bsz*Hsz], g_h2l[Bsz*Hsz];
__device__ bf16  g_xh [Bsz*ISZ], g_xl [Bsz*ISZ];
__device__ bf16  g_x2h[Bsz*Hsz], g_x2l[Bsz*Hsz];
__device__ bf16  g_hm1h[Bsz*Hsz], g_hm1l[Bsz*Hsz];
__device__ bf16  g_hm2h[Bsz*Hsz], g_hm2l[Bsz*Hsz];
__device__ float g_acc[2*ACH];   // split-K partial slices (full overwrite, no atomics)
__device__ int   g_cnt[128];
__device__ unsigned g_barcnt;
__device__ volatile unsigned g_bargen;

__device__ __forceinline__ float sigm(float z)  { return 1.f / (1.f + __expf(-z)); }
__device__ __forceinline__ float tanhff(float z){ return 2.f / (1.f + __expf(-2.f*z)) - 1.f; }

__device__ __forceinline__ void cpa16(unsigned int dst, const void* src) {
    asm volatile("cp.async.cg.shared.global [%0], [%1], 16;\n" :: "r"(dst), "l"(src));
}
__device__ __forceinline__ void cpa_commit() { asm volatile("cp.async.commit_group;\n"); }
__device__ __forceinline__ void cpa_waitall() { asm volatile("cp.async.wait_all;\n"); }

// ---------------- grid barrier (hot spin) ---------------------------------------
__device__ __forceinline__ void gridbar() {
    __syncthreads();
    if (threadIdx.x == 0) {
        __threadfence();
        unsigned gen = g_bargen;
        if (atomicAdd(&g_barcnt, 1u) == (unsigned)(gridDim.x - 1)) {
            g_barcnt = 0;
            __threadfence();
            atomicExch((unsigned*)&g_bargen, gen + 1u);
        } else {
            while (g_bargen == gen) {}
        }
        __threadfence();
    }
    __syncthreads();
}

// ---------------- weight preconversion (once per launch) -----------------------
__global__ void preconv_kernel(
    const float* c1Q, const float* c1R, const float* c1Wih, const float* c1Whh,
    const float* c2Q, const float* c2R, const float* c2Wih, const float* c2Whh)
{
    int seg = blockIdx.y;
    const float *src = 0, *src2 = 0;
    int K = 0, N = 0, LD = 0, K1 = 0, lstm = 0;
    size_t dst = 0;
    switch (seg) {
        case 0: case 1: case 2:
            src = c1Q + (size_t)seg*131072; K = 1024; N = 128; LD = 1024; dst = OQ1(seg); break;
        case 3: case 4:
            src = c1R + (size_t)(seg-3)*131072; K = 128; N = 1024; LD = 128; dst = OR1(seg-3); break;
        case 5:
            src = c1Wih; src2 = c1Whh; K = 1152; N = 4096; K1 = 128; lstm = 1; dst = OL1; break;
        case 6: case 7: case 8:
            src = c2Q + (size_t)(seg-6)*1048576; K = 1024; N = 1024; LD = 1024; dst = OQ2(seg-6); break;
        case 9: case 10:
            src = c2R + (size_t)(seg-9)*1048576; K = 1024; N = 1024; LD = 1024; dst = OR2(seg-9); break;
        default:
            src = c2Wih; src2 = c2Whh; K = 2048; N = 4096; K1 = 1024; lstm = 1; dst = OL2; break;
    }
    size_t tot = (size_t)K * N;
    for (size_t i = (size_t)blockIdx.x*blockDim.x + threadIdx.x; i < tot;
         i += (size_t)gridDim.x*blockDim.x) {
        int k = (int)(i / N), n = (int)(i % N);
        float v;
        if (!lstm) {
            v = src[(size_t)n*LD + k];
        } else {
            int g = n & 3, u = n >> 2;
            int row = g*Hsz + u;
            v = (k < K1) ? src[(size_t)row*K1 + k] : src2[(size_t)row*Hsz + (k - K1)];
        }
        bf16 h = __float2bfloat16(v);
        g_wh[dst + i] = h;
        g_wl[dst + i] = __float2bfloat16(v - __bfloat162float(h));
    }
}

// ---------------- phase descriptor ---------------------------------------------
struct P {
    const bf16 *A1h, *A1l, *A2h, *A2l; int K1, Ktot;
    size_t woff;
    int N, kch, lstm;
    const float *b1, *b2;
    const float *mult; int mstride;
    float *out; bf16 *outh, *outl; int ostride;
    float *fc, *fh; bf16 *fhh, *fhl;
};

// one GEMM phase on a 64-CTA half-grid: 128 x NSTRIP tile, split-K into disjoint
// g_acc slices (no atomics), (1<<KSH)-k macro-tiles, cp.async bf16 hi/lo,
// 3-term bf16 wmma; C fragments stored DIRECTLY to global slice (no smem
// roundtrip); fused epilogue on last-arriving CTA per tile.
template<int NSHIFT, int KSH>
__device__ __noinline__ void run_phase(const P p, int cta, float* accbase, int* cnt) {
    constexpr int NSTRIP = 1 << NSHIFT;
    constexpr int KW     = 1 << KSH;               // k per macro-tile (32 or 64)
    constexpr int WPITCH = NSTRIP + 8;
    constexpr int NW     = (NSHIFT >= 6) ? 4 : 2;
    constexpr int MW     = 16 / NW;
    constexpr int MFR    = 8 / MW;
    constexpr int NFR    = NSTRIP / (16 * NW);
    constexpr int AP     = KW + 8;                 // A pitch (bf16 elems)
    constexpr int ABUFE  = 2 * 128 * AP;           // hi+lo elems per A buffer
    constexpr int WBUFE  = 2 * KW * WPITCH;        // hi+lo elems per W buffer
    constexpr int TS     = 128 * NSTRIP;
    constexpr int ACH_CH = 128 * KW / 8;           // A 16B chunks per plane
    constexpr int WCH    = KW * (NSTRIP / 8);      // W 16B chunks per plane
    extern __shared__ float smf[];
    bf16* const sb = (bf16*)smf;
    bf16* const Wb = sb + 2 * ABUFE;
    __shared__ int s_last;

    const int ntiles = p.N >> NSHIFT;
    if (cta >= ntiles * p.kch) return;

    const int tid = threadIdx.x;
    const int wid = tid >> 5;
    const int tile = cta / p.kch, kc = cta - tile * p.kch;
    const int n0 = tile << NSHIFT;
    const int KL = p.Ktot / p.kch;
    const int k0 = kc * KL;
    const int niter = KL >> KSH;
    const int wm = wid % MW, wn = wid / MW;

    wmma::fragment<wmma::accumulator, 16, 16, 16, float> C[MFR * NFR];
    #pragma unroll
    for (int i = 0; i < MFR * NFR; i++) wmma::fill_fragment(C[i], 0.f);

    const bf16* WHg = g_wh + p.woff;
    const bf16* WLg = g_wl + p.woff;
    const unsigned int asmA = (unsigned int)__cvta_generic_to_shared(sb);
    const unsigned int asmW = (unsigned int)__cvta_generic_to_shared(Wb);

    auto issueA = [&](int buf, int kg) {
        constexpr int TOT = 2 * ACH_CH;
        #pragma unroll
        for (int i = 0; i < (TOT + TPB - 1) / TPB; i++) {
            int o = tid + i * TPB;
            if ((TOT % TPB) == 0 || o < TOT) {
                int pl = o / ACH_CH;
                int rem = o - pl * ACH_CH;
                int r = rem / (KW / 8), c = rem - r * (KW / 8);
                int k = kg + (c << 3);
                const bf16* src;
                if (k < p.K1) src = (pl ? p.A1l : p.A1h) + (size_t)r * p.K1 + k;
                else          src = (pl ? p.A2l : p.A2h) + (size_t)r * Hsz + (k - p.K1);
                unsigned int d = asmA +
                    (unsigned int)(buf * ABUFE + pl * 128 * AP + r * AP + (c << 3)) * 2u;
                cpa16(d, src);
            }
        }
    };
    auto issueW = [&](int buf, int kg) {
        constexpr int TOT = 2 * WCH;
        #pragma unroll
        for (int i = 0; i < (TOT + TPB - 1) / TPB; i++) {
            int o = tid + i * TPB;
            if ((TOT % TPB) == 0 || o < TOT) {
                int pl = o / WCH;
                int rem = o - pl * WCH;
                int kk = rem / (NSTRIP / 8), c = rem - kk * (NSTRIP / 8);
                size_t s = (size_t)(kg + kk) * p.N + n0 + (c << 3);
                unsigned int d = asmW +
                    (unsigned int)(buf * WBUFE + pl * KW * WPITCH + kk * WPITCH + (c << 3)) * 2u;
                cpa16(d, (pl ? WLg : WHg) + s);
            }
        }
    };
    auto compute = [&](int buf) {
        const bf16* AH = sb + buf * ABUFE;
        const bf16* AL = AH + 128 * AP;
        const bf16* WH = Wb + buf * WBUFE;
        const bf16* WL = WH + KW * WPITCH;
        #pragma unroll
        for (int ks = 0; ks < KW / 16; ++ks) {
            wmma::fragment<wmma::matrix_b, 16,16,16, bf16, wmma::row_major> bH[NFR], bL[NFR];
            #pragma unroll
            for (int nf = 0; nf < NFR; ++nf) {
                int ncol = (wn * NFR + nf) * 16;
                wmma::load_matrix_sync(bH[nf], WH + ks * 16 * WPITCH + ncol, WPITCH);
                wmma::load_matrix_sync(bL[nf], WL + ks * 16 * WPITCH + ncol, WPITCH);
            }
            #pragma unroll
            for (int mf = 0; mf < MFR; ++mf) {
                int mrow = (wm * MFR + mf) * 16;
                wmma::fragment<wmma::matrix_a, 16,16,16, bf16, wmma::row_major> aH, aL;
                wmma::load_matrix_sync(aH, AH + mrow * AP + ks * 16, AP);
                wmma::load_matrix_sync(aL, AL + mrow * AP + ks * 16, AP);
                #pragma unroll
                for (int nf = 0; nf < NFR; ++nf) {
                    // 3-term: hi*hi + hi*lo + lo*hi (lo*lo ~2^-18, negligible)
                    wmma::mma_sync(C[mf*NFR+nf], aH, bH[nf], C[mf*NFR+nf]);
                    wmma::mma_sync(C[mf*NFR+nf], aH, bL[nf], C[mf*NFR+nf]);
                    wmma::mma_sync(C[mf*NFR+nf], aL, bH[nf], C[mf*NFR+nf]);
                }
            }
        }
    };

    // ---- pipelined K loop ----
    issueA(0, k0); issueW(0, k0); cpa_commit();
    cpa_waitall();
    __syncthreads();
    for (int it = 0; it < niter; ++it) {
        const int cur = it & 1;
        const bool more = (it + 1 < niter);
        if (more) {
            issueA(cur ^ 1, k0 + ((it + 1) << KSH));
            issueW(cur ^ 1, k0 + ((it + 1) << KSH));
            cpa_commit();
        }
        compute(cur);
        cpa_waitall();
        __syncthreads();
    }

    // ---- store C fragments DIRECTLY to global split-K slice ----
    float* slice = accbase + (size_t)(tile * p.kch + kc) * TS;
    #pragma unroll
    for (int mf = 0; mf < MFR; ++mf)
        #pragma unroll
        for (int nf = 0; nf < NFR; ++nf)
            wmma::store_matrix_sync(slice + ((wm * MFR + mf) * 16) * NSTRIP + (wn * NFR + nf) * 16,
                                    C[mf*NFR+nf], NSTRIP, wmma::mem_row_major);
    __threadfence();
    __syncthreads();
    if (tid == 0) s_last = (atomicAdd(&cnt[tile], 1) == p.kch - 1) ? 1 : 0;
    __syncthreads();

    if (s_last) {
        if (tid == 0) cnt[tile] = 0;
        __threadfence();
        float* base0 = accbase + (size_t)(tile * p.kch) * TS;
        for (int e = tid * 4; e < TS; e += TPB * 4) {
            float4 s4 = __ldcg((const float4*)(base0 + e));
            for (int k2 = 1; k2 < p.kch; ++k2) {
                float4 t4 = __ldcg((const float4*)(base0 + (size_t)k2 * TS + e));
                s4.x += t4.x; s4.y += t4.y; s4.z += t4.z; s4.w += t4.w;
            }
            int m = e >> NSHIFT, ln = e & (NSTRIP - 1);
            if (!p.lstm) {
                int n = n0 + ln;
                float4 mu = __ldcg((const float4*)(p.mult + (size_t)m * p.mstride + n));
                float v0 = 2.f * sigm(s4.x + p.b1[n+0]) * mu.x;
                float v1 = 2.f * sigm(s4.y + p.b1[n+1]) * mu.y;
                float v2 = 2.f * sigm(s4.z + p.b1[n+2]) * mu.z;
                float v3 = 2.f * sigm(s4.w + p.b1[n+3]) * mu.w;
                size_t o = (size_t)m * p.ostride + n;
                __stcg((float4*)(p.out + o), make_float4(v0, v1, v2, v3));
                bf16 a0 = __float2bfloat16(v0), a1 = __float2bfloat16(v1);
                bf16 a2 = __float2bfloat16(v2), a3 = __float2bfloat16(v3);
                unsigned hp0 = (unsigned)__bfloat16_as_ushort(a0) |
                               ((unsigned)__bfloat16_as_ushort(a1) << 16);
                unsigned hp1 = (unsigned)__bfloat16_as_ushort(a2) |
                               ((unsigned)__bfloat16_as_ushort(a3) << 16);
                __stcg((uint2*)((unsigned short*)p.outh + o), make_uint2(hp0, hp1));
                bf16 l0 = __float2bfloat16(v0 - __bfloat162float(a0));
                bf16 l1 = __float2bfloat16(v1 - __bfloat162float(a1));
                bf16 l2 = __float2bfloat16(v2 - __bfloat162float(a2));
                bf16 l3 = __float2bfloat16(v3 - __bfloat162float(a3));
                unsigned lp0 = (unsigned)__bfloat16_as_ushort(l0) |
                               ((unsigned)__bfloat16_as_ushort(l1) << 16);
                unsigned lp1 = (unsigned)__bfloat16_as_ushort(l2) |
                               ((unsigned)__bfloat16_as_ushort(l3) << 16);
                __stcg((uint2*)((unsigned short*)p.outl + o), make_uint2(lp0, lp1));
            } else {
                int u = (n0 + ln) >> 2;
                float zi = s4.x + p.b1[u]         + p.b2[u];
                float zf = s4.y + p.b1[Hsz+u]     + p.b2[Hsz+u];
                float zg = s4.z + p.b1[2*Hsz+u]   + p.b2[2*Hsz+u];
                float zo = s4.w + p.b1[3*Hsz+u]   + p.b2[3*Hsz+u];
                float cn = sigm(zf) * __ldcg(p.fc + (size_t)m*Hsz + u) + sigm(zi) * tanhff(zg);
                float hn = sigm(zo) * tanhff(cn);
                __stcg(p.fc + (size_t)m*Hsz + u, cn);
                __stcg(p.fh + (size_t)m*Hsz + u, hn);
                bf16 bh = __float2bfloat16(hn);
                __stcg((unsigned short*)p.fhh + (size_t)m*Hsz + u, __bfloat16_as_ushort(bh));
                __stcg((unsigned short*)p.fhl + (size_t)m*Hsz + u,
                       __bfloat16_as_ushort(__float2bfloat16(hn - __bfloat162float(bh))));
            }
        }
    }
}

__device__ __forceinline__ P mogP(const bf16* Ah, const bf16* Al, int K, size_t woff,
                                  int N, int kch, const float* bias,
                                  const float* mult, int mstride,
                                  float* out, bf16* outh, bf16* outl, int ostride) {
    P p;
    p.A1h = Ah; p.A1l = Al; p.A2h = Ah; p.A2l = Al; p.K1 = K; p.Ktot = K;
    p.woff = woff; p.N = N; p.kch = kch; p.lstm = 0;
    p.b1 = bias; p.b2 = bias;
    p.mult = mult; p.mstride = mstride;
    p.out = out; p.outh = outh; p.outl = outl; p.ostride = ostride;
    p.fc = 0; p.fh = 0; p.fhh = 0; p.fhl = 0;
    return p;
}

__device__ __forceinline__ P lstmP(const bf16* A1h, const bf16* A1l, int K1,
                                   const bf16* A2h, const bf16* A2l, int Ktot,
                                   size_t woff, const float* bih, const float* bhh,
                                   float* fc, float* fh, bf16* fhh, bf16* fhl, int kch) {
    P p;
    p.A1h = A1h; p.A1l = A1l; p.A2h = A2h; p.A2l = A2l; p.K1 = K1; p.Ktot = Ktot;
    p.woff = woff; p.N = 4096; p.kch = kch; p.lstm = 1;
    p.b1 = bih; p.b2 = bhh;
    p.mult = 0; p.mstride = 0; p.out = 0; p.outh = 0; p.outl = 0; p.ostride = 0;
    p.fc = fc; p.fh = fh; p.fhh = fhh; p.fhl = fhl;
    return p;
}

__global__ void __launch_bounds__(TPB, 1) mog_kernel(
    const float* in_seq,
    const float* c1Qb, const float* c1Rb, const float* c1bih, const float* c1bhh,
    const float* c2Qb, const float* c2Rb, const float* c2bih, const float* c2bhh,
    const float* linW, const float* linb, float* out)
{
    for (int i = blockIdx.x*TPB + threadIdx.x; i < Bsz*Hsz; i += NB*TPB) {
        g_h1[i] = 0.f; g_c1[i] = 0.f; g_h2[i] = 0.f; g_c2[i] = 0.f;
        unsigned short z = 0;
        ((unsigned short*)g_h1h)[i] = z; ((unsigned short*)g_h1l)[i] = z;
        ((unsigned short*)g_h2h)[i] = z; ((unsigned short*)g_h2l)[i] = z;
    }
    gridbar();

    const int ca = (blockIdx.x < 64);          // chain A = layer1(step s); B = layer2(step s-1)
    const int rc = ca ? blockIdx.x : blockIdx.x - 64;
    float* accA = g_acc;        float* accB = g_acc + ACH;
    int*   cntA = g_cnt;        int*   cntB = g_cnt + 64;

    for (int s = 0; s <= Tsz; ++s) {
        const int dA = (s < Tsz), dB = (s > 0);
        // slot 1: aQ0(s) || bQ0(s-1)
        if (ca) { if (dA) run_phase<5,5>(mogP(g_h1h, g_h1l, Hsz, OQ1(0), ISZ, 16, c1Qb,
                                              in_seq + (size_t)s*ISZ, Tsz*ISZ,
                                              g_x, g_xh, g_xl, ISZ), rc, accA, cntA); }
        else    { if (dB) run_phase<6,6>(mogP(g_h2h, g_h2l, Hsz, OQ2(0), Hsz, 4, c2Qb,
                                              g_h1, Hsz, g_x2, g_x2h, g_x2l, Hsz), rc, accB, cntB); }
        gridbar();
        // slot 2: aR0(s) || bR0(s-1)
        if (ca) { if (dA) run_phase<5,5>(mogP(g_xh, g_xl, ISZ, OR1(0), Hsz, 2, c1Rb,
                                              g_h1, Hsz, g_hm1, g_hm1h, g_hm1l, Hsz), rc, accA, cntA); }
        else    { if (dB) run_phase<6,6>(mogP(g_x2h, g_x2l, Hsz, OR2(0), Hsz, 4, c2Rb,
                                              g_h2, Hsz, g_hm2, g_hm2h, g_hm2l, Hsz), rc, accB, cntB); }
        gridbar();
        // slot 3: aQ1(s) || bQ1(s-1)
        if (ca) { if (dA) run_phase<5,5>(mogP(g_hm1h, g_hm1l, Hsz, OQ1(1), ISZ, 16, c1Qb + ISZ,
                                              g_x, ISZ, g_x, g_xh, g_xl, ISZ), rc, accA, cntA); }
        else    { if (dB) run_phase<6,6>(mogP(g_hm2h, g_hm2l, Hsz, OQ2(1), Hsz, 4, c2Qb + Hsz,
                                              g_x2, Hsz, g_x2, g_x2h, g_x2l, Hsz), rc, accB, cntB); }
        gridbar();
        // slot 4: aR1(s) || bR1(s-1)
        if (ca) { if (dA) run_phase<5,5>(mogP(g_xh, g_xl, ISZ, OR1(1), Hsz, 2, c1Rb + Hsz,
                                              g_hm1, Hsz, g_hm1, g_hm1h, g_hm1l, Hsz), rc, accA, cntA); }
        else    { if (dB) run_phase<6,6>(mogP(g_x2h, g_x2l, Hsz, OR2(1), Hsz, 4, c2Rb + Hsz,
                                              g_hm2, Hsz, g_hm2, g_hm2h, g_hm2l, Hsz), rc, accB, cntB); }
        gridbar();
        // slot 5: aQ2(s) || bQ2(s-1)
        if (ca) { if (dA) run_phase<5,5>(mogP(g_hm1h, g_hm1l, Hsz, OQ1(2), ISZ, 16, c1Qb + 2*ISZ,
                                              g_x, ISZ, g_x, g_xh, g_xl, ISZ), rc, accA, cntA); }
        else    { if (dB) run_phase<6,6>(mogP(g_hm2h, g_hm2l, Hsz, OQ2(2), Hsz, 4, c2Qb + 2*Hsz,
                                              g_x2, Hsz, g_x2, g_x2h, g_x2l, Hsz), rc, accB, cntB); }
        gridbar();
        // slot 6: aLSTM1(s) || bLSTM2(s-1)   (k64 macro-tiles: niter 9 / 16)
        if (ca) { if (dA) run_phase<7,6>(lstmP(g_xh, g_xl, ISZ, g_hm1h, g_hm1l, ISZ + Hsz, OL1,
                                               c1bih, c1bhh, g_c1, g_h1, g_h1h, g_h1l, 2),
                                         rc, accA, cntA); }
        else    { if (dB) run_phase<7,6>(lstmP(g_x2h, g_x2l, Hsz, g_hm2h, g_hm2l, 2*Hsz, OL2,
                                               c2bih, c2bhh, g_c2, g_h2, g_h2h, g_h2l, 2),
                                         rc, accB, cntB); }
        gridbar();
    }

    // final linear: out[b] = h2[b,:] . linW + linb
    if (blockIdx.x == 0 && threadIdx.x < 256) {
        int tid = threadIdx.x;
        int b = tid >> 1, half = tid & 1;
        const float* hrow = g_h2 + b*Hsz + half*512;
        const float* w    = linW + half*512;
        float s = 0.f;
        for (int j = 0; j < 512; ++j) s += __ldcg(hrow + j) * w[j];
        s += __shfl_xor_sync(0xffffffffu, s, 1);
        if (half == 0) out[b] = s + linb[0];
    }
}

extern "C" void kernel_launch(void* const* d_in, const int* in_sizes, int n_in,
                              void* d_out, int out_size) {
    (void)in_sizes; (void)n_in; (void)out_size;
    cudaFuncSetAttribute(mog_kernel, cudaFuncAttributeMaxDynamicSharedMemorySize,
                         SMEM_BYTES);
    const float* in_seq = (const float*)d_in[0];
    const float* c1Q    = (const float*)d_in[1];
    const float* c1Qb   = (const float*)d_in[2];
    const float* c1R    = (const float*)d_in[3];
    const float* c1Rb   = (const float*)d_in[4];
    const float* c1Wih  = (const float*)d_in[5];
    const float* c1Whh  = (const float*)d_in[6];
    const float* c1bih  = (const float*)d_in[7];
    const float* c1bhh  = (const float*)d_in[8];
    const float* c2Q    = (const float*)d_in[9];
    const float* c2Qb   = (const float*)d_in[10];
    const float* c2R    = (const float*)d_in[11];
    const float* c2Rb   = (const float*)d_in[12];
    const float* c2Wih  = (const float*)d_in[13];
    const float* c2Whh  = (const float*)d_in[14];
    const float* c2bih  = (const float*)d_in[15];
    const float* c2bhh  = (const float*)d_in[16];
    const float* linW   = (const float*)d_in[17];
    const float* linb   = (const float*)d_in[18];

    preconv_kernel<<<dim3(256, 12), 256>>>(c1Q, c1R, c1Wih, c1Whh,
                                           c2Q, c2R, c2Wih, c2Whh);
    mog_kernel<<<NB, TPB, SMEM_BYTES>>>(in_seq,
                                        c1Qb, c1Rb, c1bih, c1bhh,
                                        c2Qb, c2Rb, c2bih, c2bhh,
                                        linW, linb, (float*)d_out);
}